// round 17
// baseline (speedup 1.0000x reference)
#include <cuda_runtime.h>
#include <cuda_fp16.h>
#include <cstdint>
#include <cstddef>

#define DM 63
#define DD 64
#define NR_MAX 256
#define NE_MAX 16384
#define B_MAX 2048
#define TMAIN 128
#define TILE  128
#define WSTR  65

// ---- scratch (static __device__ globals; no runtime allocation) ----
__device__ float g_Wg[2][(size_t)NR_MAX * DD * DD];   // gelu(W) rows, row 63 + col 63 zero
__device__ float g_iv[2][NR_MAX * DD];                // 2/s_j (j=63 -> 0)
__device__ float g_G [2][NR_MAX * 224];               // intra-segment Gram pairs
__device__ float g_off[2][NR_MAX * DD];               // mobius offset per relation
__device__ float g_off2[2][NR_MAX];                   // sum(off^2)
__device__ float g_p63[NR_MAX * DD];                  // tail: P e62, [0]=0
__device__ float g_ofu[NR_MAX * DD];                  // tail: P D off_sp, [0]=off0
__device__ float g_ttl[B_MAX * DD];                   // tail: P D th_sp per b, [0]=0
__device__ float g_sc[B_MAX * 8];                     // {O2m,OTm,T2m,thb,th0,off0,off2,-}
__device__ __half g_eh[(size_t)NE_MAX * DD];          // fp16 mirror of ent

__device__ __constant__ int c_pa[28] = {0,0,1,0,1,2,0,1,2,3,0,1,2,3,4,0,1,2,3,4,5,0,1,2,3,4,5,6};
__device__ __constant__ int c_pb[28] = {1,2,2,3,3,3,4,4,4,4,5,5,5,5,5,6,6,6,6,6,6,7,7,7,7,7,7,7};

__device__ __forceinline__ float gelu_exact(float x) {
    return 0.5f * x * (1.0f + erff(x * 0.70710678118654752f));
}

__device__ __forceinline__ float wbfly(float v) {
    #pragma unroll
    for (int o = 16; o; o >>= 1) v += __shfl_xor_sync(0xffffffffu, v, o);
    return v;
}

// ============================================================================
// Rank-8 reflection segment applied to a warp-held vector (see R12 notes).
// ============================================================================
template<bool FWD>
__device__ __forceinline__ void apply_seg(
    float& v0, float& v1, int lane,
    const float* __restrict__ W, int wstride,
    const float* __restrict__ iv, const float* __restrict__ G, int seg)
{
    int lo = seg * 8;
    float w0[8], w1[8], d[8], ivv[8], g[28];
    #pragma unroll
    for (int i = 0; i < 8; i++) {
        const float* row = W + (size_t)(lo + i) * wstride;
        w0[i] = (lane >= 1) ? row[lane - 1] : 0.0f;
        w1[i] = row[lane + 31];
        ivv[i] = iv[lo + i];
    }
    #pragma unroll
    for (int p = 0; p < 28; p++) g[p] = G[seg * 28 + p];
    #pragma unroll
    for (int i = 0; i < 8; i++) d[i] = fmaf(w0[i], v0, w1[i] * v1);
    #pragma unroll
    for (int o = 16; o; o >>= 1) {
        #pragma unroll
        for (int i = 0; i < 8; i++) d[i] += __shfl_xor_sync(0xffffffffu, d[i], o);
    }
    float c[8];
    if (FWD) {
        c[0] = d[0] * ivv[0];
        c[1] = (d[1] - c[0]*g[0]) * ivv[1];
        c[2] = (d[2] - c[0]*g[1] - c[1]*g[2]) * ivv[2];
        c[3] = (d[3] - c[0]*g[3] - c[1]*g[4] - c[2]*g[5]) * ivv[3];
        c[4] = (d[4] - c[0]*g[6] - c[1]*g[7] - c[2]*g[8] - c[3]*g[9]) * ivv[4];
        c[5] = (d[5] - c[0]*g[10] - c[1]*g[11] - c[2]*g[12] - c[3]*g[13] - c[4]*g[14]) * ivv[5];
        c[6] = (d[6] - c[0]*g[15] - c[1]*g[16] - c[2]*g[17] - c[3]*g[18] - c[4]*g[19] - c[5]*g[20]) * ivv[6];
        c[7] = (d[7] - c[0]*g[21] - c[1]*g[22] - c[2]*g[23] - c[3]*g[24] - c[4]*g[25] - c[5]*g[26] - c[6]*g[27]) * ivv[7];
    } else {
        c[7] = d[7] * ivv[7];
        c[6] = (d[6] - c[7]*g[27]) * ivv[6];
        c[5] = (d[5] - c[7]*g[26] - c[6]*g[20]) * ivv[5];
        c[4] = (d[4] - c[7]*g[25] - c[6]*g[19] - c[5]*g[14]) * ivv[4];
        c[3] = (d[3] - c[7]*g[24] - c[6]*g[18] - c[5]*g[13] - c[4]*g[9]) * ivv[3];
        c[2] = (d[2] - c[7]*g[23] - c[6]*g[17] - c[5]*g[12] - c[4]*g[8] - c[3]*g[5]) * ivv[2];
        c[1] = (d[1] - c[7]*g[22] - c[6]*g[16] - c[5]*g[11] - c[4]*g[7] - c[3]*g[4] - c[2]*g[2]) * ivv[1];
        c[0] = (d[0] - c[7]*g[21] - c[6]*g[15] - c[5]*g[10] - c[4]*g[6] - c[3]*g[3] - c[2]*g[1] - c[1]*g[0]) * ivv[0];
    }
    float s0 = 0.0f, s1 = 0.0f;
    #pragma unroll
    for (int i = 0; i < 8; i++) { s0 = fmaf(c[i], w0[i], s0); s1 = fmaf(c[i], w1[i], s1); }
    v0 -= s0; v1 -= s1;
}

// ============================================================================
// K1: per-segment gelu + norms + Gram + offsets (z==0, warp1) +
//     fp16 ent-mirror conversion (z==8 plane). grid (NR, 2, 9), block 64.
// ============================================================================
__global__ void __launch_bounds__(64) k_seg(
    const float* __restrict__ Wh,  const float* __restrict__ Wtt,
    const float* __restrict__ rch, const float* __restrict__ dirh,
    const float* __restrict__ rct, const float* __restrict__ dirt,
    const float* __restrict__ ent, int NE)
{
    int r = blockIdx.x, side = blockIdx.y, seg = blockIdx.z;
    int tid = threadIdx.x, lane = tid & 31, wid = tid >> 5;

    if (seg == 8) {
        // fp16 mirror: chunk = r + side*NR over 2*NR chunks, float4 -> half2x2
        int chunk = r + side * gridDim.x;
        int nch   = 2 * gridDim.x;
        int nv    = (NE * DD) >> 2;
        const float4* src = (const float4*)ent;
        uint2* dst = (uint2*)g_eh;
        for (int i = chunk * 64 + tid; i < nv; i += nch * 64) {
            float4 f = src[i];
            __half2 h0 = __floats2half2_rn(f.x, f.y);
            __half2 h1 = __floats2half2_rn(f.z, f.w);
            uint2 o;
            o.x = *(unsigned*)&h0;
            o.y = *(unsigned*)&h1;
            dst[i] = o;
        }
        return;
    }

    const float* Wemb = side ? Wtt : Wh;
    __shared__ __align__(16) float WgS[8][WSTR];
    float* gW = &g_Wg[side][(size_t)r * DD * DD];
    int j0 = seg * 8;

    // gelu 8 rows -> smem + global (pads: j==63 or k==63 -> 0)
    const float* wb = Wemb + (size_t)r * DM * DM;
    #pragma unroll
    for (int ii = 0; ii < 8; ii++) {
        int idx = ii * 64 + tid;
        int jj = idx >> 6, k = idx & 63;
        int j = j0 + jj;
        float v = 0.0f;
        if (j < DM && k < DM) v = gelu_exact(wb[j * DM + k]);
        WgS[jj][k] = v;
        gW[(size_t)j * DD + k] = v;
    }
    __syncthreads();

    // 36 tasks: t<8 norms -> iv; t in [8,36) Gram pairs
    if (tid < 36) {
        const float *ra, *rb;
        if (tid < 8) { ra = rb = WgS[tid]; }
        else { int q = tid - 8; ra = WgS[c_pa[q]]; rb = WgS[c_pb[q]]; }
        float a0 = 0, a1 = 0, a2 = 0, a3 = 0;
        #pragma unroll
        for (int k = 0; k < DD; k += 4) {
            a0 = fmaf(ra[k    ], rb[k    ], a0);
            a1 = fmaf(ra[k + 1], rb[k + 1], a1);
            a2 = fmaf(ra[k + 2], rb[k + 2], a2);
            a3 = fmaf(ra[k + 3], rb[k + 3], a3);
        }
        float dot = (a0 + a1) + (a2 + a3);
        if (tid < 8) {
            int j = j0 + tid;
            g_iv[side][r * DD + j] = (j < DM) ? 2.0f / dot : 0.0f;
        } else {
            g_G[side][r * 224 + seg * 28 + (tid - 8)] = dot;
        }
    }

    // offset = expmap(c, 0.1 * normalize(d + <c,d> c)) — z==0 block, warp 1
    if (seg == 0 && wid == 1) {
        const float* rc = side ? rct  : rch;
        const float* dw = side ? dirt : dirh;
        float cv0 = rc[r * DD + lane], cv1 = rc[r * DD + lane + 32];
        float dv0 = dw[r * DD + lane], dv1 = dw[r * DD + lane + 32];
        float inner = wbfly(fmaf(cv0, dv0, cv1 * dv1));
        float t0 = fmaf(inner, cv0, dv0), t1 = fmaf(inner, cv1, dv1);
        float tn2 = wbfly(fmaf(t0, t0, t1 * t1));
        float inv = 1.0f / (sqrtf(tn2) + 1e-6f);
        float u0v = 0.1f * t0 * inv, u1v = 0.1f * t1 * inv;
        float su2 = wbfly(fmaf(u0v, u0v, u1v * u1v));
        float ut  = __shfl_sync(0xffffffffu, u0v, 0);
        float lin = su2 - 2.0f * ut * ut;
        float nrm = fminf(sqrtf(fmaxf(lin, 1e-8f)), 2.5f);
        float ch = coshf(nrm), sh = sinhf(nrm) / nrm;
        float o0 = fmaf(ch, cv0, sh * u0v);
        float o1 = fmaf(ch, cv1, sh * u1v);
        g_off[side][r * DD + lane]      = o0;
        g_off[side][r * DD + lane + 32] = o1;
        float o2 = wbfly(fmaf(o0, o0, o1 * o1));
        if (lane == 0) g_off2[side][r] = o2;
    }
}

// ============================================================================
// K2: merged head pipeline + side-1 relation chains. grid (B/2 + NR), block 64.
// ============================================================================
__global__ void __launch_bounds__(64) k_hc(
    const float* __restrict__ ent, const float* __restrict__ bias_head,
    const int* __restrict__ u_idx, const int* __restrict__ r_idx,
    const float* __restrict__ fsh, const float* __restrict__ fst, int Bh)
{
    __shared__ float ivS[DD];
    __shared__ float GS[224];

    int blk = blockIdx.x;
    int tid = threadIdx.x, lane = tid & 31, wid = tid >> 5;

    if (blk < Bh) {
        int b = blk * 2 + wid;
        int u = u_idx[b], r = r_idx[b];
        float fsH = fsh[0], fsT = fst[0];
        int l = lane;

        float v0 = ent[(size_t)u * DD + l];
        float v1 = ent[(size_t)u * DD + l + 32];

        {   // y_sp = D (P^T x_sp): forward chain, then flip comp62
            const float* W  = &g_Wg[0][(size_t)r * DD * DD];
            const float* iv = &g_iv[0][r * DD];
            const float* G  = &g_G[0][r * 224];
            #pragma unroll 1
            for (int s = 0; s < 8; s++) apply_seg<true>(v0, v1, l, W, DD, iv, G, s);
        }
        if (l == 31) v1 *= fsH;

        float oh0 = g_off[0][r * DD + l];
        float oh1 = g_off[0][r * DD + l + 32];
        float x2 = wbfly(fmaf(v0, v0, v1 * v1));
        float xy = wbfly(fmaf(v0, oh0, v1 * oh1));
        float y2  = g_off2[0][r];
        float A   = 1.0f + 2.0f * xy + y2;
        float Bc  = 1.0f - x2;
        float den = 1.0f + 2.0f * xy + x2 * y2 + 1e-15f;
        float rd  = 1.0f / den;
        float th0c = fmaf(A, v0, Bc * oh0) * rd;
        float th1c = fmaf(A, v1, Bc * oh1) * rd;

        float t0 = th0c, t1 = th1c;
        if (l == 31) t1 *= fsT;
        {
            const float* W  = &g_Wg[1][(size_t)r * DD * DD];
            const float* iv = &g_iv[1][r * DD];
            const float* G  = &g_G[1][r * 224];
            #pragma unroll 1
            for (int s = 7; s >= 0; s--) apply_seg<false>(t0, t1, l, W, DD, iv, G, s);
        }
        g_ttl[b * DD + l]      = (l >= 1) ? t0 : 0.0f;
        g_ttl[b * DD + l + 32] = t1;

        float ot0 = g_off[1][r * DD + l];
        float ot1 = g_off[1][r * DD + l + 32];
        float e0  = (l >= 1) ? 1.0f : 0.0f;
        float pO2 = wbfly(fmaf(e0 * ot0, ot0,  ot1 * ot1));
        float pOT = wbfly(fmaf(e0 * ot0, th0c, ot1 * th1c));
        float pT2 = wbfly(fmaf(e0 * th0c, th0c, th1c * th1c));
        if (l == 0) {
            float* sc = &g_sc[b * 8];
            sc[0] = pO2;
            sc[1] = pOT;
            sc[2] = pT2;
            sc[3] = tanhf(bias_head[u]);
            sc[4] = th0c;
            sc[5] = ot0;
            sc[6] = g_off2[1][r];
            sc[7] = 0.0f;
        }
    } else {
        int r = blk - Bh;
        float fs = fst[0];

        ivS[tid] = g_iv[1][r * DD + tid];
        for (int i = tid; i < 224; i += 64) GS[i] = g_G[1][r * 224 + i];
        __syncthreads();

        const float* W = &g_Wg[1][(size_t)r * DD * DD];
        if (wid == 0) {
            float o0 = g_off[1][r * DD + lane];
            float o1 = g_off[1][r * DD + lane + 32];
            float off0save = __shfl_sync(0xffffffffu, o0, 0);
            float v0 = (lane >= 1) ? o0 : 0.0f;
            float v1 = o1;
            if (lane == 31) v1 *= fs;
            #pragma unroll 1
            for (int s = 7; s >= 0; s--) apply_seg<false>(v0, v1, lane, W, DD, ivS, GS, s);
            g_ofu[r * DD + lane]      = (lane >= 1) ? v0 : off0save;
            g_ofu[r * DD + lane + 32] = v1;
        } else {
            float v0 = 0.0f;
            float v1 = (lane == 31) ? 1.0f : 0.0f;
            #pragma unroll 1
            for (int s = 7; s >= 0; s--) apply_seg<false>(v0, v1, lane, W, DD, ivS, GS, s);
            g_p63[r * DD + lane]      = (lane >= 1) ? v0 : 0.0f;
            g_p63[r * DD + lane + 32] = v1;
        }
    }
}

// ============================================================================
// K3: main scoring. grid (B, N/128), block 128. fp16 gather (128 B/row) +
//   fp32 y0 sidecar + software-pipelined loads. Lane h owns elems [8h,8h+8).
// ============================================================================
__global__ void __launch_bounds__(TMAIN) k_main(
    const float* __restrict__ ent, const float* __restrict__ bias_tail,
    const int* __restrict__ r_idx, const int* __restrict__ v_idx,
    const float* __restrict__ fst,
    float* __restrict__ out, int N)
{
    __shared__ __align__(16) float4 res4[TILE];
    __shared__ int   vs[TILE];
    __shared__ __align__(16) float pv[DD], ov[DD], tl[DD];
    __shared__ float scs[8];

    int b     = blockIdx.x;
    int tbase = blockIdx.y * TILE;
    int tid   = threadIdx.x;
    if (tbase >= N) return;
    int nt = min(TILE, N - tbase);
    int r  = r_idx[b];

    if (tid < DD) {
        pv[tid] = g_p63[r * DD + tid];
        ov[tid] = (tid == 0) ? 0.0f : g_ofu[r * DD + tid];   // time term handled in epilogue
        tl[tid] = g_ttl[b * DD + tid];
    }
    if (tid < 8) scs[tid] = g_sc[b * 8 + tid];
    vs[tid] = (tid < nt) ? v_idx[b * N + tbase + tid] : 0;
    float fsv  = fst[0];
    float fsm1 = fsv * fsv - 1.0f;
    __syncthreads();

    float btraw = bias_tail[vs[tid < nt ? tid : 0]];

    int h = tid & 7;          // lane within 8-lane row group
    int g = tid >> 3;         // row slot
    // per-lane vector slices: elements [8h, 8h+8)
    float pa[8], oa[8], ta[8];
    #pragma unroll
    for (int j = 0; j < 8; j++) {
        pa[j] = pv[8 * h + j];
        oa[j] = ov[8 * h + j];
        ta[j] = tl[8 * h + j];
    }

    // software pipeline: prefetch row i+1 while reducing row i
    uint4 xh = ((const uint4*)(g_eh + (size_t)vs[g] * DD))[h];
    float x0f = ent[(size_t)vs[g] * DD];

    #pragma unroll
    for (int i = 0; i < 8; i++) {
        uint4 xh_n;
        float x0_n = 0.0f;
        if (i < 7) {
            int rown = (i + 1) * 16 + g;
            xh_n = ((const uint4*)(g_eh + (size_t)vs[rown] * DD))[h];
            x0_n = ent[(size_t)vs[rown] * DD];
        }

        const __half2* hp = (const __half2*)&xh;
        float2 f0 = __half22float2(hp[0]);
        float2 f1 = __half22float2(hp[1]);
        float2 f2 = __half22float2(hp[2]);
        float2 f3 = __half22float2(hp[3]);

        float s1 = f0.x * pa[0];
        float s2 = f0.x * oa[0];
        float s3 = f0.x * ta[0];
        s1 = fmaf(f0.y, pa[1], s1); s2 = fmaf(f0.y, oa[1], s2); s3 = fmaf(f0.y, ta[1], s3);
        s1 = fmaf(f1.x, pa[2], s1); s2 = fmaf(f1.x, oa[2], s2); s3 = fmaf(f1.x, ta[2], s3);
        s1 = fmaf(f1.y, pa[3], s1); s2 = fmaf(f1.y, oa[3], s2); s3 = fmaf(f1.y, ta[3], s3);
        s1 = fmaf(f2.x, pa[4], s1); s2 = fmaf(f2.x, oa[4], s2); s3 = fmaf(f2.x, ta[4], s3);
        s1 = fmaf(f2.y, pa[5], s1); s2 = fmaf(f2.y, oa[5], s2); s3 = fmaf(f2.y, ta[5], s3);
        s1 = fmaf(f3.x, pa[6], s1); s2 = fmaf(f3.x, oa[6], s2); s3 = fmaf(f3.x, ta[6], s3);
        s1 = fmaf(f3.y, pa[7], s1); s2 = fmaf(f3.y, oa[7], s2); s3 = fmaf(f3.y, ta[7], s3);

        #pragma unroll
        for (int o = 4; o; o >>= 1) {
            s1 += __shfl_down_sync(0xffffffffu, s1, o, 8);
            s2 += __shfl_down_sync(0xffffffffu, s2, o, 8);
            s3 += __shfl_down_sync(0xffffffffu, s3, o, 8);
        }
        if (h == 0) res4[i * 16 + g] = make_float4(s1, s2, s3, x0f);

        xh = xh_n;
        x0f = x0_n;
    }
    __syncthreads();

    if (tid < nt) {
        float4 rr = res4[tid];
        float s1 = rr.x, syoP = rr.y, syt = rr.z, y0 = rr.w;  // syoP: spatial only

        float O2m = scs[0], OTm = scs[1], T2m = scs[2], thb = scs[3];
        float th0 = scs[4], off0 = scs[5], off2 = scs[6];

        float syo = fmaf(y0, off0, syoP);                  // fp32 time term
        float syy_m = fmaf(fsm1, s1 * s1, fmaf(y0, y0, -1.0f));
        float syy   = syy_m + y0 * y0;

        float A   = 1.0f + 2.0f * syo + off2;
        float Bv  = 1.0f - syy;
        float den = 1.0f + 2.0f * syo + syy * off2 + 1e-15f;
        float rd  = 1.0f / den;
        float a   = A * rd, bs = Bv * rd;
        float d0  = fmaf(a, y0, fmaf(bs, off0, -th0));
        float cross = fmaf(bs, syoP, -syt);
        float bterm = fmaf(bs, fmaf(bs, O2m, -2.0f * OTm), T2m);
        float sum1  = fmaf(a * a, syy_m, fmaf(2.0f * a, cross, bterm));
        float mkv   = sum1 - d0 * d0;

        out[(size_t)b * N + tbase + tid] = 8.0f - mkv + thb + tanhf(btraw);
    }
}

// ============================================================================
extern "C" void kernel_launch(void* const* d_in, const int* in_sizes, int n_in,
                              void* d_out, int out_size)
{
    (void)n_in; (void)out_size;
    const float* ent  = (const float*)d_in[0];
    const float* Wh   = (const float*)d_in[1];
    const float* Wtt  = (const float*)d_in[2];
    const float* rch  = (const float*)d_in[3];
    const float* dirh = (const float*)d_in[4];
    const float* rct  = (const float*)d_in[5];
    const float* dirt = (const float*)d_in[6];
    const float* bh   = (const float*)d_in[7];
    const float* bt   = (const float*)d_in[8];
    const float* fsh  = (const float*)d_in[9];
    const float* fst  = (const float*)d_in[10];
    const int* u_idx  = (const int*)d_in[11];
    const int* r_idx  = (const int*)d_in[12];
    const int* v_idx  = (const int*)d_in[13];
    float* out = (float*)d_out;

    int NE = in_sizes[0] / DD;       // 14541
    int NR = in_sizes[3] / DD;       // 237
    int B  = in_sizes[11];           // 1024
    int N  = in_sizes[13] / B;       // 512
    int S  = (N + TILE - 1) / TILE;  // 4
    int Bh = B / 2;                  // 512 head blocks (2 rows each)

    k_seg<<<dim3(NR, 2, 9), 64>>>(Wh, Wtt, rch, dirh, rct, dirt, ent, NE);
    k_hc<<<Bh + NR, 64>>>(ent, bh, u_idx, r_idx, fsh, fst, Bh);
    k_main<<<dim3(B, S), TMAIN>>>(ent, bt, r_idx, v_idx, fst, out, N);
}